// round 1
// baseline (speedup 1.0000x reference)
#include <cuda_runtime.h>

// KVCache append: out = [k_cache ++ k_val  (axis=2)] then [v_cache ++ v_val].
// B=4, H=32, S=4096, T=1, D=128, fp32.
// Pure streaming copy — HBM-bound. All accesses are 16B-vectorized and
// coalesced; index math is pure block-coordinate arithmetic (no divides).

#define KV_B 4
#define KV_H 32
#define KV_S 4096
#define KV_T 1
#define KV_D 128

#define ROWS        (KV_B * KV_H)            // 128 (b,h) rows
#define ROW4_IN     (KV_S * KV_D / 4)        // 131072 float4 per cache row
#define ROW4_OUT    ((KV_S + KV_T) * KV_D / 4) // 131104 float4 per output row
#define HALF4       (ROWS * ROW4_OUT)        // float4 per output tensor (k or v)
#define VAL4_PER_ROW (KV_T * KV_D / 4)       // 32 float4 appended per row

// ---------------------------------------------------------------------------
// Kernel 1: bulk cache copy. grid = (ROW4_IN/256, ROWS, 2), block = 256.
// One float4 load + one float4 store per thread; fully coalesced.
// ---------------------------------------------------------------------------
__global__ void __launch_bounds__(256)
kv_copy_cache(const float4* __restrict__ k_cache,
              const float4* __restrict__ v_cache,
              float4* __restrict__ out)
{
    const int half = blockIdx.z;                 // 0 = k, 1 = v
    const int row  = blockIdx.y;                 // (b,h) flattened
    const long i   = (long)blockIdx.x * blockDim.x + threadIdx.x; // 0..ROW4_IN-1

    const float4* __restrict__ src = half ? v_cache : k_cache;
    out[(long)half * HALF4 + (long)row * ROW4_OUT + i] =
        src[(long)row * ROW4_IN + i];
}

// ---------------------------------------------------------------------------
// Kernel 2: append the new token (tiny: 2 * 128 rows * 32 float4 = 8192 vec4).
// ---------------------------------------------------------------------------
__global__ void __launch_bounds__(256)
kv_copy_val(const float4* __restrict__ k_val,
            const float4* __restrict__ v_val,
            float4* __restrict__ out)
{
    const int idx = blockIdx.x * blockDim.x + threadIdx.x; // 0..8191
    const int half = idx >> 12;                  // /4096
    const int rem  = idx & 4095;
    const int row  = rem >> 5;                   // /32
    const int d4   = rem & 31;

    const float4* __restrict__ src = half ? v_val : k_val;
    out[(long)half * HALF4 + (long)row * ROW4_OUT + ROW4_IN + d4] =
        src[row * VAL4_PER_ROW + d4];
}

extern "C" void kernel_launch(void* const* d_in, const int* in_sizes, int n_in,
                              void* d_out, int out_size)
{
    const float4* k_cache = (const float4*)d_in[0];
    const float4* v_cache = (const float4*)d_in[1];
    const float4* k_val   = (const float4*)d_in[2];
    const float4* v_val   = (const float4*)d_in[3];
    float4* out = (float4*)d_out;

    dim3 grid_cache(ROW4_IN / 256, ROWS, 2);   // (512, 128, 2)
    kv_copy_cache<<<grid_cache, 256>>>(k_cache, v_cache, out);

    const int val_total = 2 * ROWS * VAL4_PER_ROW; // 8192
    kv_copy_val<<<val_total / 256, 256>>>(k_val, v_val, out);
}

// round 2
// speedup vs baseline: 1.0312x; 1.0312x over previous
#include <cuda_runtime.h>

// KVCache append, fused single kernel.
// B=4, H=32, S=4096, T=1, D=128, fp32.
// out = [k_cache ++ k_val (axis=2)] then [v_cache ++ v_val].
// HBM-bound streaming copy: 537MB in + 537MB out. 16B vectors, 4x unroll
// per thread for MLP, streaming cache hints (no reuse), val-append fused
// as one extra x-block per (row, half) to kill the second launch.

#define KV_S 4096
#define KV_T 1
#define KV_D 128

#define ROWS         128                         // B*H (b,h) rows
#define ROW4_IN      (KV_S * KV_D / 4)           // 131072 float4 per cache row
#define ROW4_OUT     ((KV_S + KV_T) * KV_D / 4)  // 131104 float4 per output row
#define HALF4        ((long)ROWS * ROW4_OUT)     // float4 per output tensor
#define VAL4_PER_ROW (KV_T * KV_D / 4)           // 32 float4 appended per row

#define UNROLL     4
#define TPB        256
#define CHUNK      (TPB * UNROLL)                // 1024 float4 per block
#define CACHE_BLKS (ROW4_IN / CHUNK)             // 128 x-blocks for the copy

__global__ void __launch_bounds__(TPB)
kv_append(const float4* __restrict__ k_cache,
          const float4* __restrict__ v_cache,
          const float4* __restrict__ k_val,
          const float4* __restrict__ v_val,
          float4* __restrict__ out)
{
    const int half = blockIdx.z;   // 0 = k, 1 = v
    const int row  = blockIdx.y;   // (b,h) flattened

    float4* __restrict__ dst = out + (long)half * HALF4 + (long)row * ROW4_OUT;

    if (blockIdx.x < CACHE_BLKS) {
        // Bulk cache copy: 4 coalesced float4 per thread.
        const float4* __restrict__ src =
            (half ? v_cache : k_cache) + (long)row * ROW4_IN;
        const long base = (long)blockIdx.x * CHUNK + threadIdx.x;

        float4 r[UNROLL];
        #pragma unroll
        for (int u = 0; u < UNROLL; u++)
            r[u] = __ldcs(&src[base + u * TPB]);
        #pragma unroll
        for (int u = 0; u < UNROLL; u++)
            __stcs(&dst[base + u * TPB], r[u]);
    } else if (threadIdx.x < VAL4_PER_ROW) {
        // Append the new token for this (row, half): 32 float4.
        const float4* __restrict__ sv = half ? v_val : k_val;
        __stcs(&dst[ROW4_IN + threadIdx.x],
               __ldcs(&sv[row * VAL4_PER_ROW + threadIdx.x]));
    }
}

extern "C" void kernel_launch(void* const* d_in, const int* in_sizes, int n_in,
                              void* d_out, int out_size)
{
    const float4* k_cache = (const float4*)d_in[0];
    const float4* v_cache = (const float4*)d_in[1];
    const float4* k_val   = (const float4*)d_in[2];
    const float4* v_val   = (const float4*)d_in[3];
    float4* out = (float4*)d_out;

    dim3 grid(CACHE_BLKS + 1, ROWS, 2);  // (129, 128, 2)
    kv_append<<<grid, TPB>>>(k_cache, v_cache, k_val, v_val, out);
}

// round 3
// speedup vs baseline: 1.0316x; 1.0004x over previous
#include <cuda_runtime.h>

// KVCache append, fused single kernel. B=4,H=32,S=4096,T=1,D=128 fp32.
// out = [k_cache ++ k_val (axis=2)] then [v_cache ++ v_val].
// HBM-bound stream: 537MB in + 537MB out. 8x float4 per thread (128B/128B)
// for deep MLP, all loads issued before all stores, streaming cache hints.

#define KV_S 4096
#define KV_T 1
#define KV_D 128

#define ROWS         128                         // B*H rows
#define ROW4_IN      (KV_S * KV_D / 4)           // 131072 float4 per cache row
#define ROW4_OUT     ((KV_S + KV_T) * KV_D / 4)  // 131104 float4 per output row
#define HALF4        ((long)ROWS * ROW4_OUT)     // float4 per output tensor
#define VAL4_PER_ROW (KV_T * KV_D / 4)           // 32 float4 appended per row

#define UNROLL     8
#define TPB        256
#define CHUNK      (TPB * UNROLL)                // 2048 float4 per block
#define CACHE_BLKS (ROW4_IN / CHUNK)             // 64 x-blocks per (row,half)

__global__ void __launch_bounds__(TPB)
kv_append(const float4* __restrict__ k_cache,
          const float4* __restrict__ v_cache,
          const float4* __restrict__ k_val,
          const float4* __restrict__ v_val,
          float4* __restrict__ out)
{
    const int half = blockIdx.z;   // 0 = k, 1 = v
    const int row  = blockIdx.y;   // (b,h) flattened

    float4* __restrict__ dst = out + (long)half * HALF4 + (long)row * ROW4_OUT;

    if (blockIdx.x < CACHE_BLKS) {
        const float4* __restrict__ src =
            (half ? v_cache : k_cache) + (long)row * ROW4_IN;
        const long base = (long)blockIdx.x * CHUNK + threadIdx.x;

        float4 r[UNROLL];
        #pragma unroll
        for (int u = 0; u < UNROLL; u++)
            r[u] = __ldcs(&src[base + u * TPB]);
        #pragma unroll
        for (int u = 0; u < UNROLL; u++)
            __stcs(&dst[base + u * TPB], r[u]);
    } else if (threadIdx.x < VAL4_PER_ROW) {
        // Append the new token for this (row, half): 32 float4 = 512B.
        const float4* __restrict__ sv = half ? v_val : k_val;
        __stcs(&dst[ROW4_IN + threadIdx.x],
               __ldcs(&sv[row * VAL4_PER_ROW + threadIdx.x]));
    }
}

extern "C" void kernel_launch(void* const* d_in, const int* in_sizes, int n_in,
                              void* d_out, int out_size)
{
    const float4* k_cache = (const float4*)d_in[0];
    const float4* v_cache = (const float4*)d_in[1];
    const float4* k_val   = (const float4*)d_in[2];
    const float4* v_val   = (const float4*)d_in[3];
    float4* out = (float4*)d_out;

    dim3 grid(CACHE_BLKS + 1, ROWS, 2);  // (65, 128, 2)
    kv_append<<<grid, TPB>>>(k_cache, v_cache, k_val, v_val, out);
}